// round 2
// baseline (speedup 1.0000x reference)
#include <cuda_runtime.h>
#include <cuda_bf16.h>

#define NB 4
#define CC 24
#define EE 16
#define PP (768*768)
#define B1 288
#define PXB (PP/B1)        /* 2048 pixels per block */
#define ITERS (PXB/256)    /* 8 iterations of 256 pixels */

__device__ float g_sums[NB*CC*EE];
__device__ float g_cnt[NB*CC];
__device__ float g_var[NB*CC];
__device__ float g_means[NB*CC*EE];
__device__ float g_trip[NB];

// ---------------------------------------------------------------------------
// K0: zero the atomic accumulators (deterministic per launch)
// ---------------------------------------------------------------------------
__global__ void k_zero() {
    int t = blockIdx.x * 256 + threadIdx.x;
    if (t < NB*CC*EE) g_sums[t] = 0.f;
    if (t < NB*CC) { g_cnt[t] = 0.f; g_var[t] = 0.f; }
}

// ---------------------------------------------------------------------------
// K1: per-segment counts + embedding sums.
// Per-warp privatized shared bins; intra-warp conflicts handled with
// match_any + single REDUX-max rank rounds (non-atomic vector RMW).
// ---------------------------------------------------------------------------
__global__ __launch_bounds__(256) void k_sums(const float* __restrict__ x,
                                              const int* __restrict__ tgt) {
    const int n = blockIdx.y;
    __shared__ __align__(16) float bins[8][CC][EE];   // 12 KB
    __shared__ float cnts[8][CC];
    const int tid  = threadIdx.x;
    const int wid  = tid >> 5;
    const int lane = tid & 31;

    for (int i = tid; i < 8*CC*EE; i += 256) (&bins[0][0][0])[i] = 0.f;
    for (int i = tid; i < 8*CC;    i += 256) (&cnts[0][0])[i]   = 0.f;
    __syncthreads();

    const float* xn = x   + (size_t)n * EE * PP;
    const int*   tn = tgt + (size_t)n * PP;
    const unsigned lmask = (1u << lane) - 1u;

    int pbase = blockIdx.x * PXB + tid;
    for (int it = 0; it < ITERS; ++it, pbase += 256) {
        const int p = pbase;
        const int seg = tn[p];
        float4 v[4];
#pragma unroll
        for (int j = 0; j < 4; ++j) {
            v[j].x = xn[(4*j+0)*PP + p];
            v[j].y = xn[(4*j+1)*PP + p];
            v[j].z = xn[(4*j+2)*PP + p];
            v[j].w = xn[(4*j+3)*PP + p];
        }
        const unsigned mm = __match_any_sync(0xffffffffu, seg);
        const int rank = __popc(mm & lmask);
        const int rmax = __reduce_max_sync(0xffffffffu, rank);
        float4* bp = reinterpret_cast<float4*>(&bins[wid][seg][0]);
        for (int r = 0; r <= rmax; ++r) {
            if (rank == r) {
#pragma unroll
                for (int j = 0; j < 4; ++j) {
                    float4 t = bp[j];
                    t.x += v[j].x; t.y += v[j].y;
                    t.z += v[j].z; t.w += v[j].w;
                    bp[j] = t;
                }
                if (r == 0) cnts[wid][seg] += (float)__popc(mm);
            }
            __syncwarp();
        }
    }
    __syncthreads();

    for (int i = tid; i < CC*EE; i += 256) {
        float s = 0.f;
#pragma unroll
        for (int w = 0; w < 8; ++w) s += (&bins[w][0][0])[i];
        atomicAdd(&g_sums[n*CC*EE + i], s);
    }
    for (int i = tid; i < CC; i += 256) {
        float s = 0.f;
#pragma unroll
        for (int w = 0; w < 8; ++w) s += cnts[w][i];
        atomicAdd(&g_cnt[n*CC + i], s);
    }
}

// ---------------------------------------------------------------------------
// K2: means = sums / counts
// ---------------------------------------------------------------------------
__global__ void k_means() {
    int t = threadIdx.x;
    if (t < NB*CC) {
        float inv = 1.f / g_cnt[t];
#pragma unroll
        for (int e = 0; e < EE; ++e)
            g_means[t*EE + e] = g_sums[t*EE + e] * inv;
    }
}

// ---------------------------------------------------------------------------
// K3: variance pass — hinged distance to own mean, scattered per segment.
// ---------------------------------------------------------------------------
__global__ __launch_bounds__(256) void k_var(const float* __restrict__ x,
                                             const int* __restrict__ tgt) {
    const int n = blockIdx.y;
    __shared__ float ms[CC][17];     // padded to avoid bank aliasing
    __shared__ float vb[8][CC];
    const int tid  = threadIdx.x;
    const int wid  = tid >> 5;
    const int lane = tid & 31;

    for (int i = tid; i < CC*EE; i += 256) ms[i/EE][i%EE] = g_means[n*CC*EE + i];
    for (int i = tid; i < 8*CC;  i += 256) (&vb[0][0])[i] = 0.f;
    __syncthreads();

    const float* xn = x   + (size_t)n * EE * PP;
    const int*   tn = tgt + (size_t)n * PP;
    const unsigned lmask = (1u << lane) - 1u;

    int pbase = blockIdx.x * PXB + tid;
    for (int it = 0; it < ITERS; ++it, pbase += 256) {
        const int p = pbase;
        const int seg = tn[p];
        float d2 = 0.f;
#pragma unroll
        for (int e = 0; e < EE; ++e) {
            float diff = xn[e*PP + p] - ms[seg][e];
            d2 += diff * diff;
        }
        float h = sqrtf(d2) - 0.5f;
        h = fmaxf(h, 0.f);
        h = h * h;

        const unsigned mm = __match_any_sync(0xffffffffu, seg);
        const int rank = __popc(mm & lmask);
        const int rmax = __reduce_max_sync(0xffffffffu, rank);
        for (int r = 0; r <= rmax; ++r) {
            if (rank == r) vb[wid][seg] += h;
            __syncwarp();
        }
    }
    __syncthreads();

    for (int i = tid; i < CC; i += 256) {
        float s = 0.f;
#pragma unroll
        for (int w = 0; w < 8; ++w) s += vb[w][i];
        atomicAdd(&g_var[n*CC + i], s);
    }
}

// ---------------------------------------------------------------------------
// K4: triplet term per sample (A = R = 200, 40k pairs — trivial)
// ---------------------------------------------------------------------------
__global__ __launch_bounds__(256) void k_triplet(const int* __restrict__ ea,
                                                 const int* __restrict__ er) {
    const int n = blockIdx.x;
    __shared__ float cm[CC][EE];
    __shared__ float da[200], dr[200];
    __shared__ int a0[200], a1[200], r0s[200], r1s[200];
    __shared__ float reds[256];
    __shared__ int   redc[256];
    const int tid = threadIdx.x;

    for (int i = tid; i < CC*EE; i += 256) (&cm[0][0])[i] = g_means[n*CC*EE + i];
    __syncthreads();

    if (tid < 200) {
        int i0 = ea[n*400 + tid], i1 = ea[n*400 + 200 + tid];
        a0[tid] = i0; a1[tid] = i1;
        float s = 0.f;
#pragma unroll
        for (int e = 0; e < EE; ++e) {
            float df = cm[i0][e] - cm[i1][e] + 1e-6f;
            s += df * df;
        }
        da[tid] = s;
        i0 = er[n*400 + tid]; i1 = er[n*400 + 200 + tid];
        r0s[tid] = i0; r1s[tid] = i1;
        s = 0.f;
#pragma unroll
        for (int e = 0; e < EE; ++e) {
            float df = cm[i0][e] - cm[i1][e] + 1e-6f;
            s += df * df;
        }
        dr[tid] = s;
    }
    __syncthreads();

    float sum = 0.f; int cnt = 0;
    for (int idx = tid; idx < 200*200; idx += 256) {
        int a = idx / 200, rr = idx % 200;
        int m = (a0[a] == r0s[rr]) + (a0[a] == r1s[rr]) +
                (a1[a] == r0s[rr]) + (a1[a] == r1s[rr]);
        if (m == 1) {
            float t = 0.5f * (da[a] - dr[rr]) + 0.01f;
            if (t > 0.f) { sum += t; cnt++; }
        }
    }
    reds[tid] = sum; redc[tid] = cnt;
    __syncthreads();
    for (int s = 128; s > 0; s >>= 1) {
        if (tid < s) { reds[tid] += reds[tid + s]; redc[tid] += redc[tid + s]; }
        __syncthreads();
    }
    if (tid == 0) g_trip[n] = (redc[0] > 0) ? reds[0] / (float)redc[0] : 0.f;
}

// ---------------------------------------------------------------------------
// K5: finalize — variance term, regularizer, combine, /16
// ---------------------------------------------------------------------------
__global__ void k_final(float* __restrict__ out) {
    __shared__ float red[128];
    const int t = threadIdx.x;
    float acc = 0.f;
    if (t < NB*CC) {
        float vt = g_var[t] / g_cnt[t];
        float s2 = 0.f;
#pragma unroll
        for (int e = 0; e < EE; ++e) {
            float m = g_means[t*EE + e];
            s2 += m * m;
        }
        float rg = sqrtf(s2) - 1.f;
        acc = (vt + rg * rg) * (1.f / (float)CC);
    }
    if (t < NB) acc += g_trip[t];
    red[t] = acc;
    __syncthreads();
    for (int s = 64; s > 0; s >>= 1) {
        if (t < s) red[t] += red[t + s];
        __syncthreads();
    }
    if (t == 0) out[0] = red[0] / 16.f;
}

// ---------------------------------------------------------------------------
extern "C" void kernel_launch(void* const* d_in, const int* in_sizes, int n_in,
                              void* d_out, int out_size) {
    const float* x   = (const float*)d_in[0];
    const int*   tgt = (const int*)d_in[1];
    const int*   ea  = (const int*)d_in[2];
    const int*   er  = (const int*)d_in[3];
    float* out = (float*)d_out;

    k_zero<<<24, 256>>>();
    dim3 g(B1, NB);
    k_sums<<<g, 256>>>(x, tgt);
    k_means<<<1, 128>>>();
    k_var<<<g, 256>>>(x, tgt);
    k_triplet<<<NB, 256>>>(ea, er);
    k_final<<<1, 128>>>(out);
}

// round 4
// speedup vs baseline: 1.7837x; 1.7837x over previous
#include <cuda_runtime.h>
#include <cuda_bf16.h>

#define NB 4
#define CC 24
#define EE 16
#define PP (768*768)
#define B1 288
#define PXB (PP/B1)        /* 2048 pixels per block */
#define ITERS (PXB/256)    /* 8 iterations of 256 pixels */

__device__ float g_sums[NB*CC*EE];
__device__ float g_cnt[NB*CC];
__device__ float g_var[NB*CC];
__device__ float g_means[NB*CC*EE];
__device__ float g_trip[NB];

// ---------------------------------------------------------------------------
// K0: zero the atomic accumulators (deterministic per launch)
// ---------------------------------------------------------------------------
__global__ void k_zero() {
    int t = blockIdx.x * 256 + threadIdx.x;
    if (t < NB*CC*EE) g_sums[t] = 0.f;
    if (t < NB*CC) { g_cnt[t] = 0.f; g_var[t] = 0.f; }
}

// ---------------------------------------------------------------------------
// K1: per-segment counts + embedding sums.
// match_any groups -> shfl sliding-window tree -> leader-only RMW into
// per-warp padded bins (20-float rows kill LDS.128 bank-quad conflicts).
// ---------------------------------------------------------------------------
__global__ __launch_bounds__(256) void k_sums(const float* __restrict__ x,
                                              const int* __restrict__ tgt) {
    const int n = blockIdx.y;
    __shared__ __align__(16) float bins[8][CC][20];   // padded rows: 15.4 KB
    __shared__ float cnts[8][CC];
    const int tid  = threadIdx.x;
    const int wid  = tid >> 5;
    const int lane = tid & 31;

    for (int i = tid; i < 8*CC*20; i += 256) (&bins[0][0][0])[i] = 0.f;
    for (int i = tid; i < 8*CC;    i += 256) (&cnts[0][0])[i]   = 0.f;
    __syncthreads();

    const float* xn = x   + (size_t)n * EE * PP;
    const int*   tn = tgt + (size_t)n * PP;
    const unsigned lmask = (1u << lane) - 1u;

    int pbase = blockIdx.x * PXB + tid;
    for (int it = 0; it < ITERS; ++it, pbase += 256) {
        const int p = pbase;
        const int seg = tn[p];
        float v[EE];
#pragma unroll
        for (int e = 0; e < EE; ++e) v[e] = xn[e*PP + p];

        const unsigned mm = __match_any_sync(0xffffffffu, seg);
        const int rank = __popc(mm & lmask);
        const int gsz  = __popc(mm);
        const int gmax = __reduce_max_sync(0xffffffffu, gsz);

        for (int st = 1; st < gmax; st <<= 1) {
            const unsigned src = __fns(mm, 0, rank + st + 1);
            const bool valid = (src != 0xffffffffu);
            const int sl = valid ? (int)src : lane;
#pragma unroll
            for (int e = 0; e < EE; ++e) {
                const float ov = __shfl_sync(0xffffffffu, v[e], sl);
                if (valid) v[e] += ov;
            }
        }

        if (rank == 0) {                     // group leader, distinct seg per leader
            float4* bp = reinterpret_cast<float4*>(&bins[wid][seg][0]);
#pragma unroll
            for (int j = 0; j < 4; ++j) {
                float4 t = bp[j];
                t.x += v[4*j+0]; t.y += v[4*j+1];
                t.z += v[4*j+2]; t.w += v[4*j+3];
                bp[j] = t;
            }
            cnts[wid][seg] += (float)gsz;
        }
    }
    __syncthreads();

    for (int i = tid; i < CC*EE; i += 256) {
        float s = 0.f;
#pragma unroll
        for (int w = 0; w < 8; ++w) s += bins[w][i/EE][i%EE];
        atomicAdd(&g_sums[n*CC*EE + i], s);
    }
    for (int i = tid; i < CC; i += 256) {
        float s = 0.f;
#pragma unroll
        for (int w = 0; w < 8; ++w) s += cnts[w][i];
        atomicAdd(&g_cnt[n*CC + i], s);
    }
}

// ---------------------------------------------------------------------------
// K2: means = sums / counts
// ---------------------------------------------------------------------------
__global__ void k_means() {
    int t = threadIdx.x;
    if (t < NB*CC) {
        float inv = 1.f / g_cnt[t];
#pragma unroll
        for (int e = 0; e < EE; ++e)
            g_means[t*EE + e] = g_sums[t*EE + e] * inv;
    }
}

// ---------------------------------------------------------------------------
// K3: variance pass — hinged distance to own mean, shfl-tree scatter.
// ---------------------------------------------------------------------------
__global__ __launch_bounds__(256) void k_var(const float* __restrict__ x,
                                             const int* __restrict__ tgt) {
    const int n = blockIdx.y;
    __shared__ float ms[CC][17];     // padded to avoid bank aliasing
    __shared__ float vb[8][CC];
    const int tid  = threadIdx.x;
    const int wid  = tid >> 5;
    const int lane = tid & 31;

    for (int i = tid; i < CC*EE; i += 256) ms[i/EE][i%EE] = g_means[n*CC*EE + i];
    for (int i = tid; i < 8*CC;  i += 256) (&vb[0][0])[i] = 0.f;
    __syncthreads();

    const float* xn = x   + (size_t)n * EE * PP;
    const int*   tn = tgt + (size_t)n * PP;
    const unsigned lmask = (1u << lane) - 1u;

    int pbase = blockIdx.x * PXB + tid;
    for (int it = 0; it < ITERS; ++it, pbase += 256) {
        const int p = pbase;
        const int seg = tn[p];
        float d2 = 0.f;
#pragma unroll
        for (int e = 0; e < EE; ++e) {
            float diff = xn[e*PP + p] - ms[seg][e];
            d2 += diff * diff;
        }
        float h = sqrtf(d2) - 0.5f;
        h = fmaxf(h, 0.f);
        h = h * h;

        const unsigned mm = __match_any_sync(0xffffffffu, seg);
        const int rank = __popc(mm & lmask);
        const int gsz  = __popc(mm);
        const int gmax = __reduce_max_sync(0xffffffffu, gsz);

        for (int st = 1; st < gmax; st <<= 1) {
            const unsigned src = __fns(mm, 0, rank + st + 1);
            const bool valid = (src != 0xffffffffu);
            const int sl = valid ? (int)src : lane;
            const float oh = __shfl_sync(0xffffffffu, h, sl);
            if (valid) h += oh;
        }

        if (rank == 0) vb[wid][seg] += h;
    }
    __syncthreads();

    for (int i = tid; i < CC; i += 256) {
        float s = 0.f;
#pragma unroll
        for (int w = 0; w < 8; ++w) s += vb[w][i];
        atomicAdd(&g_var[n*CC + i], s);
    }
}

// ---------------------------------------------------------------------------
// K4: triplet term per sample (A = R = 200, 40k pairs — trivial)
// ---------------------------------------------------------------------------
__global__ __launch_bounds__(256) void k_triplet(const int* __restrict__ ea,
                                                 const int* __restrict__ er) {
    const int n = blockIdx.x;
    __shared__ float cm[CC][EE];
    __shared__ float da[200], dr[200];
    __shared__ int a0[200], a1[200], r0s[200], r1s[200];
    __shared__ float reds[256];
    __shared__ int   redc[256];
    const int tid = threadIdx.x;

    for (int i = tid; i < CC*EE; i += 256) (&cm[0][0])[i] = g_means[n*CC*EE + i];
    __syncthreads();

    if (tid < 200) {
        int i0 = ea[n*400 + tid], i1 = ea[n*400 + 200 + tid];
        a0[tid] = i0; a1[tid] = i1;
        float s = 0.f;
#pragma unroll
        for (int e = 0; e < EE; ++e) {
            float df = cm[i0][e] - cm[i1][e] + 1e-6f;
            s += df * df;
        }
        da[tid] = s;
        i0 = er[n*400 + tid]; i1 = er[n*400 + 200 + tid];
        r0s[tid] = i0; r1s[tid] = i1;
        s = 0.f;
#pragma unroll
        for (int e = 0; e < EE; ++e) {
            float df = cm[i0][e] - cm[i1][e] + 1e-6f;
            s += df * df;
        }
        dr[tid] = s;
    }
    __syncthreads();

    float sum = 0.f; int cnt = 0;
    for (int idx = tid; idx < 200*200; idx += 256) {
        int a = idx / 200, rr = idx % 200;
        int m = (a0[a] == r0s[rr]) + (a0[a] == r1s[rr]) +
                (a1[a] == r0s[rr]) + (a1[a] == r1s[rr]);
        if (m == 1) {
            float t = 0.5f * (da[a] - dr[rr]) + 0.01f;
            if (t > 0.f) { sum += t; cnt++; }
        }
    }
    reds[tid] = sum; redc[tid] = cnt;
    __syncthreads();
    for (int s = 128; s > 0; s >>= 1) {
        if (tid < s) { reds[tid] += reds[tid + s]; redc[tid] += redc[tid + s]; }
        __syncthreads();
    }
    if (tid == 0) g_trip[n] = (redc[0] > 0) ? reds[0] / (float)redc[0] : 0.f;
}

// ---------------------------------------------------------------------------
// K5: finalize — variance term, regularizer, combine, /16
// ---------------------------------------------------------------------------
__global__ void k_final(float* __restrict__ out) {
    __shared__ float red[128];
    const int t = threadIdx.x;
    float acc = 0.f;
    if (t < NB*CC) {
        float vt = g_var[t] / g_cnt[t];
        float s2 = 0.f;
#pragma unroll
        for (int e = 0; e < EE; ++e) {
            float m = g_means[t*EE + e];
            s2 += m * m;
        }
        float rg = sqrtf(s2) - 1.f;
        acc = (vt + rg * rg) * (1.f / (float)CC);
    }
    if (t < NB) acc += g_trip[t];
    red[t] = acc;
    __syncthreads();
    for (int s = 64; s > 0; s >>= 1) {
        if (t < s) red[t] += red[t + s];
        __syncthreads();
    }
    if (t == 0) out[0] = red[0] / 16.f;
}

// ---------------------------------------------------------------------------
extern "C" void kernel_launch(void* const* d_in, const int* in_sizes, int n_in,
                              void* d_out, int out_size) {
    const float* x   = (const float*)d_in[0];
    const int*   tgt = (const int*)d_in[1];
    const int*   ea  = (const int*)d_in[2];
    const int*   er  = (const int*)d_in[3];
    float* out = (float*)d_out;

    k_zero<<<24, 256>>>();
    dim3 g(B1, NB);
    k_sums<<<g, 256>>>(x, tgt);
    k_means<<<1, 128>>>();
    k_var<<<g, 256>>>(x, tgt);
    k_triplet<<<NB, 256>>>(ea, er);
    k_final<<<1, 128>>>(out);
}